// round 3
// baseline (speedup 1.0000x reference)
#include <cuda_runtime.h>
#include <cuda_bf16.h>
#include <math.h>

// Problem constants (fixed shapes)
#define B_ROWS 65536
#define D_DIM  256
#define L_LVL  4
#define K_CODES 2048

// GEMM tiling
#define BM 128
#define BN 128
#define BK 32
#define NTHREADS 256

// Scratch (allocation-free rule: __device__ globals)
__device__ float g_res[(size_t)B_ROWS * D_DIM];        // running residual, 64 MB
__device__ float g_e2[L_LVL * K_CODES];                // per-code squared norms (fp32, rounded from fp64)

// ---------------------------------------------------------------------------
// e2[l*K + k] = sum_d codebooks[l,k,d]^2  in fp64, rounded to fp32.
// One warp per code row.
// ---------------------------------------------------------------------------
__global__ void e2_kernel(const float* __restrict__ codebooks)
{
    int warp = (blockIdx.x * blockDim.x + threadIdx.x) >> 5;
    int lane = threadIdx.x & 31;
    if (warp >= L_LVL * K_CODES) return;
    const float* p = codebooks + (size_t)warp * D_DIM;
    double s = 0.0;
    #pragma unroll
    for (int i = 0; i < D_DIM / 32; ++i) {
        double v = (double)p[lane + 32 * i];
        s += v * v;
    }
    #pragma unroll
    for (int o = 16; o; o >>= 1) s += __shfl_xor_sync(0xffffffffu, s, o);
    if (lane == 0) g_e2[warp] = (float)s;
}

// ---------------------------------------------------------------------------
// One RQ level. Scores emulate the reference rounding chain:
//   S = fl( fl(x2 + e2[k]) - 2*dot )
// with x2/e2 correctly rounded (fp64->fp32) and dot in fp32 FFMA.
// Ties (exact equal S) break to the lower code index, matching jnp.argmin.
// Then: res -= emb[idx]  (exact elementwise fp32, same as reference)
//       quant = fl(quant + emb[idx])  (reference's qsum accumulation chain)
//       codes[b*L + level] = idx
// Block = 128 rows x all 2048 codes.
// ---------------------------------------------------------------------------
__global__ __launch_bounds__(NTHREADS, 2)
void rq_level_kernel(const float* __restrict__ residual,   // original input [B,D]
                     const float* __restrict__ codebooks,  // [L,K,D]
                     float* __restrict__ quant,            // [B,D] running qsum (d_out)
                     float* __restrict__ codes_out,        // [B,L] written as float
                     int level)
{
    __shared__ float As[BK][BM + 4];   // res chunk, K-major
    __shared__ float Bs[BK][BN + 4];   // emb chunk, K-major
    __shared__ float redV[BM][16];
    __shared__ int   redI[BM][16];
    __shared__ float sh_x2[BM];

    const float* res_in  = (level == 0) ? residual : g_res;
    float*       res_out = g_res;
    const float* emb = codebooks + (size_t)level * K_CODES * D_DIM;
    const float* e2  = g_e2 + level * K_CODES;

    const int tid  = threadIdx.x;
    const int nIdx = tid & 15;          // 0..15 (column group)
    const int mIdx = tid >> 4;          // 0..15 (row group)
    const int bm   = blockIdx.x * BM;

    const int ldd = tid & 31;           // d within chunk for tile loads
    const int ldr = tid >> 5;           // base row for tile loads (0..7)

    // ---- per-row x2 = sum(res^2) in fp64, rounded to fp32 (2 threads/row) ----
    {
        int r = tid >> 1;
        int h = tid & 1;
        const float* p = res_in + (size_t)(bm + r) * D_DIM + h * 128;
        double s = 0.0;
        #pragma unroll 16
        for (int i = 0; i < 128; ++i) {
            double v = (double)p[i];
            s += v * v;
        }
        // partner (tid^1) is in the same warp
        s += __shfl_xor_sync(0xffffffffu, s, 1);
        if (h == 0) sh_x2[r] = (float)s;
    }
    __syncthreads();

    // x2 values for the 8 rows this thread scores
    float x2v[8];
    #pragma unroll
    for (int i = 0; i < 8; ++i) {
        int r = (i < 4) ? (mIdx * 4 + i) : (64 + mIdx * 4 + (i - 4));
        x2v[i] = sh_x2[r];
    }

    float minV[8];
    int   minI[8];
    #pragma unroll
    for (int i = 0; i < 8; ++i) { minV[i] = INFINITY; minI[i] = 0; }

    for (int nt = 0; nt < K_CODES / BN; ++nt) {
        float acc[8][8];
        #pragma unroll
        for (int i = 0; i < 8; ++i)
            #pragma unroll
            for (int j = 0; j < 8; ++j) acc[i][j] = 0.f;

        for (int dc = 0; dc < D_DIM; dc += BK) {
            __syncthreads();   // previous compute done before overwrite
            #pragma unroll
            for (int i = 0; i < BM / 8; ++i) {
                int r = ldr + 8 * i;
                As[ldd][r] = res_in[(bm + r) * D_DIM + dc + ldd];
                Bs[ldd][r] = emb[(nt * BN + r) * D_DIM + dc + ldd];
            }
            __syncthreads();

            #pragma unroll 8
            for (int kk = 0; kk < BK; ++kk) {
                const float4 a0 = *(const float4*)(&As[kk][mIdx * 4]);
                const float4 a1 = *(const float4*)(&As[kk][64 + mIdx * 4]);
                const float4 b0 = *(const float4*)(&Bs[kk][nIdx * 4]);
                const float4 b1 = *(const float4*)(&Bs[kk][64 + nIdx * 4]);
                const float a[8] = {a0.x,a0.y,a0.z,a0.w, a1.x,a1.y,a1.z,a1.w};
                const float b[8] = {b0.x,b0.y,b0.z,b0.w, b1.x,b1.y,b1.z,b1.w};
                #pragma unroll
                for (int i = 0; i < 8; ++i)
                    #pragma unroll
                    for (int j = 0; j < 8; ++j)
                        acc[i][j] += a[i] * b[j];
            }
        }

        // epilogue: S = fl(fl(x2 + e2[k]) - 2*dot); running argmin, ascending k,
        // strict < keeps first occurrence (matches jnp.argmin tie-breaking)
        #pragma unroll
        for (int j = 0; j < 8; ++j) {
            int c = (j < 4) ? (nIdx * 4 + j) : (64 + nIdx * 4 + (j - 4));
            int g = nt * BN + c;
            float ek = __ldg(&e2[g]);
            #pragma unroll
            for (int i = 0; i < 8; ++i) {
                float A = __fadd_rn(x2v[i], ek);          // fl(x2 + e2)
                float s = __fmaf_rn(-2.0f, acc[i][j], A); // fl(A - 2*dot), single rounding
                if (s < minV[i]) { minV[i] = s; minI[i] = g; }
            }
        }
    }

    // cross-thread argmin reduction (16 candidates per row), lexicographic
    __syncthreads();
    #pragma unroll
    for (int i = 0; i < 8; ++i) {
        int r = (i < 4) ? (mIdx * 4 + i) : (64 + mIdx * 4 + (i - 4));
        redV[r][nIdx] = minV[i];
        redI[r][nIdx] = minI[i];
    }
    __syncthreads();

    if (tid < BM) {
        float bv = redV[tid][0];
        int   bi = redI[tid][0];
        #pragma unroll
        for (int j = 1; j < 16; ++j) {
            float v = redV[tid][j];
            int  ix = redI[tid][j];
            if (v < bv || (v == bv && ix < bi)) { bv = v; bi = ix; }
        }
        redI[tid][0] = bi;
        codes_out[(size_t)(bm + tid) * L_LVL + level] = (float)bi;
    }
    __syncthreads();

    // residual update + qsum accumulation; 2 threads per row
    {
        int r = tid >> 1;
        int h = tid & 1;
        int q = redI[r][0];
        const size_t rowoff = (size_t)(bm + r) * D_DIM + h * 128;
        const float4* rin = (const float4*)(res_in + rowoff);
        const float4* ev  = (const float4*)(emb + (size_t)q * D_DIM + h * 128);
        float4* ro = (float4*)(res_out + rowoff);
        float4* qo = (float4*)(quant + rowoff);
        #pragma unroll
        for (int i = 0; i < 32; ++i) {
            float4 a = rin[i], e = ev[i];
            ro[i] = make_float4(__fadd_rn(a.x, -e.x), __fadd_rn(a.y, -e.y),
                                __fadd_rn(a.z, -e.z), __fadd_rn(a.w, -e.w));
            if (level == 0) {
                qo[i] = e;                       // qsum = fl(0 + q) = q
            } else {
                float4 p = qo[i];
                qo[i] = make_float4(__fadd_rn(p.x, e.x), __fadd_rn(p.y, e.y),
                                    __fadd_rn(p.z, e.z), __fadd_rn(p.w, e.w));
            }
        }
    }
}

// ---------------------------------------------------------------------------
extern "C" void kernel_launch(void* const* d_in, const int* in_sizes, int n_in,
                              void* d_out, int out_size)
{
    const float* residual  = (const float*)d_in[0];   // [B, D] float32
    const float* codebooks = (const float*)d_in[1];   // [L, K, D] float32
    float* out   = (float*)d_out;
    float* quant = out;                               // [B, D]
    float* codes = out + (size_t)B_ROWS * D_DIM;      // [B, L] as float

    // per-code squared norms for all levels (fp64 -> fp32)
    e2_kernel<<<(L_LVL * K_CODES * 32 + 255) / 256, 256>>>(codebooks);

    for (int l = 0; l < L_LVL; ++l)
        rq_level_kernel<<<B_ROWS / BM, NTHREADS>>>(residual, codebooks, quant, codes, l);
}